// round 14
// baseline (speedup 1.0000x reference)
#include <cuda_runtime.h>
#include <cstdint>

// Problem constants
#define NB   64
#define NT   2048
#define EMBD 32
#define HID  256
#define KTOT (EMBD + HID)    // 288
#define USLICE 8             // unit slices (producers per group)
#define BSLICE 16            // batch slices
#define NCTA  (USLICE * BSLICE)   // 128
#define UPC   32             // units per CTA
#define NROWS (4 * UPC)      // 128 gate rows
#define BPC   (NB / BSLICE)  // 4 batches per CTA
#define NTHREADS 256         // 4 k-segments x (32 rg x 2 bq)
#define NSEG 4
#define SEGK 64

#define WJ   292             // j stride (floats), 16B-aligned
#define WRG  1188            // rg stride; %32==4; 16B-aligned
#define ZPAD 296             // z row stride; %32==8; 16B-aligned
#define GSTR 9               // partial-gate row stride
#define GSEG (NROWS * GSTR)  // 1152

// SMEM float offsets
#define W_F   0
// W size = 31*WRG + 3*WJ + KTOT = 37992 -> round to 38000
#define Z_F   38000
#define GP_F  (Z_F + BPC * ZPAD)           // 39184
#define BS_F  (GP_F + NSEG * GSEG)         // 43792
#define LEN_F (BS_F + NROWS)               // 43920
#define ML_F  (LEN_F + NB)                 // 43984
#define TOK_F (ML_F + 4)                   // 43988
#define SM_FLOATS (TOK_F + BPC * NT)       // 52180 (~209 KB)

// Persistent cross-CTA state
__device__ float g_H[2][NB * HID];        // [buf][batch*HID + unit]
__device__ int   g_flag[BSLICE][USLICE];  // steps completed by producer (us,bsl)

__global__ void lstm_init_kernel() {
    int i = threadIdx.x;
    if (i < BSLICE * USLICE) ((int*)g_flag)[i] = 0;
}

__device__ __forceinline__ float sigf(float x)  { return 1.0f / (1.0f + __expf(-x)); }
__device__ __forceinline__ float tanha(float x) { return 2.0f / (1.0f + __expf(-2.0f * x)) - 1.0f; }

__device__ __forceinline__ int ld_acq(const int* p) {
    int v;
    asm volatile("ld.acquire.gpu.b32 %0, [%1];" : "=r"(v) : "l"(p));
    return v;
}

#define LDS2U64(a, b, addr) \
    asm volatile("ld.shared.v2.u64 {%0,%1}, [%2];" : "=l"(a), "=l"(b) : "r"(addr))
#define FMA2(acc, w, z) \
    asm volatile("fma.rn.f32x2 %0, %1, %2, %0;" : "+l"(acc) : "l"(w), "l"(z))

__global__ void __launch_bounds__(NTHREADS, 1)
lstm_persist_kernel(const int* __restrict__ x,        // [NB, NT]
                    const int* __restrict__ lengths,  // [NB]
                    const float* __restrict__ emb,    // [VOCAB, EMBD]
                    const float* __restrict__ W_ih,   // [4*HID, EMBD]
                    const float* __restrict__ W_hh,   // [4*HID, HID]
                    const float* __restrict__ b_ih,   // [4*HID]
                    const float* __restrict__ b_hh,   // [4*HID]
                    float* __restrict__ out)          // [NB, 1, HID]
{
    extern __shared__ float sm[];
    float* w_s  = sm + W_F;                  // [rg 0..31][j 0..3][k 0..287]
    float* z_s  = sm + Z_F;                  // [BPC][ZPAD]  k: 0..31 xe, 32..287 h
    float* gp   = sm + GP_F;                 // [NSEG][NROWS][GSTR]
    float* bs   = sm + BS_F;                 // [NROWS]
    int* lenS   = (int*)(sm + LEN_F);        // [NB]
    int* mlS    = (int*)(sm + ML_F);
    int* tokS   = (int*)(sm + TOK_F);        // [BPC][NT]

    const int tid = threadIdx.x;
    const int cta = blockIdx.x;
    const int us  = cta & (USLICE - 1);      // 0..7
    const int bsl = cta >> 3;                // 0..15
    const int u0  = us * UPC;
    const int bb0 = bsl * BPC;

    // ---- one-time staging: W rows, biases, lengths, ALL tokens ----
    for (int idx = tid; idx < NROWS * KTOT; idx += NTHREADS) {
        int r = idx / KTOT;
        int k = idx - r * KTOT;
        int g = r >> 5, du = r & 31;
        int grow = g * HID + u0 + du;
        float v = (k < EMBD) ? W_ih[grow * EMBD + k]
                             : W_hh[grow * HID + (k - EMBD)];
        w_s[(r >> 2) * WRG + (r & 3) * WJ + k] = v;
    }
    if (tid < NROWS) {
        int g = tid >> 5, du = tid & 31;
        int grow = g * HID + u0 + du;
        bs[tid] = b_ih[grow] + b_hh[grow];
    }
    if (tid < NB) lenS[tid] = lengths[tid];
    // tokens for my 4 batches, all timesteps (coalesced)
    for (int idx = tid; idx < BPC * NT; idx += NTHREADS) {
        int b = idx >> 11, tt = idx & (NT - 1);
        tokS[b * NT + tt] = x[(bb0 + b) * NT + tt];
    }
    __syncthreads();
    if (tid == 0) {
        int m = 1;
        for (int b = 0; b < NB; b++) m = max(m, lenS[b]);
        *mlS = m;
    }
    // zero h region of z (t=0 reads zeros)
    for (int i = tid; i < BPC * HID; i += NTHREADS) {
        int b = i >> 8, u = i & 255;
        z_s[b * ZPAD + EMBD + u] = 0.0f;
    }
    __syncthreads();
    // gather xe(0) from staged tokens
    if (tid < 8 * BPC) {
        int b = tid >> 3, q = tid & 7;
        int tok = tokS[b * NT + 0];
        float4 v = ((const float4*)(emb + (size_t)tok * EMBD))[q];
        *(float4*)(z_s + b * ZPAD + q * 4) = v;
    }
    __syncthreads();
    const int maxlen = *mlS;

    // shared base for asm addressing
    uint32_t sb;
    asm("{ .reg .u64 t; cvta.to.shared.u64 t, %1; cvt.u32.u64 %0, t; }"
        : "=r"(sb) : "l"(sm));

    // GEMM mapping: tid = seg*64 + rg*2 + bq
    const int seg = tid >> 6;                // 0..3
    const int rg  = (tid >> 1) & 31;         // rows 4rg..4rg+3
    const int bq  = tid & 1;                 // batches bq, bq+2
    const uint32_t wbase = sb + (uint32_t)(W_F + rg * WRG) * 4u;
    const uint32_t wk    = wbase + (uint32_t)(EMBD + seg * SEGK) * 4u;
    const uint32_t zA    = sb + (uint32_t)(Z_F + bq * ZPAD) * 4u;
    const uint32_t zB    = zA + (uint32_t)(2 * ZPAD) * 4u;
    const uint32_t zkA   = zA + (uint32_t)(EMBD + seg * SEGK) * 4u;
    const uint32_t zkB   = zB + (uint32_t)(EMBD + seg * SEGK) * 4u;
    float* gpb = gp + seg * GSEG;

    // phase-2 mapping (tid < 128): unit u_l = tid>>2 (0..31), batch b2 = tid&3
    const int u_l = tid >> 2;
    const int b2  = tid & 3;
    const int bg  = bb0 + (b2 & 3);
    const int uu  = u0 + (u_l & 31);
    const int mylen = (tid < 128) ? lenS[bg] : 0;
    float c_r = 0.0f, h_r = 0.0f;

    // xe-prefetch mapping (tid < 32): batch tid>>3, quad tid&7
    const int xb = tid >> 3, xq = tid & 7;

    unsigned long long A[4][2];
    #pragma unroll
    for (int j = 0; j < 4; j++) { A[j][0] = 0ull; A[j][1] = 0ull; }

    // ---- prologue: seg0 accumulates W_ih . xe(0) ----
    if (seg == 0) {
        #pragma unroll
        for (int k = 0; k < EMBD; k += 4) {
            unsigned long long Z01a, Z23a, Z01b, Z23b;
            LDS2U64(Z01a, Z23a, zA + k * 4);
            LDS2U64(Z01b, Z23b, zB + k * 4);
            #pragma unroll
            for (int j = 0; j < 4; j++) {
                unsigned long long W01, W23;
                LDS2U64(W01, W23, wbase + (uint32_t)(j * WJ + k) * 4u);
                FMA2(A[j][0], W01, Z01a); FMA2(A[j][0], W23, Z23a);
                FMA2(A[j][1], W01, Z01b); FMA2(A[j][1], W23, Z23b);
            }
        }
    }

    for (int t = 0; t < maxlen; t++) {
        // ---- EARLY prefetch: emb row for xe(t+1), covered by main GEMM+phase2 ----
        float4 xe_pf;
        const bool do_xe = (tid < 32) && (t + 1 < maxlen);
        if (do_xe) {
            int tok = tokS[xb * NT + (t + 1)];
            xe_pf = ((const float4*)(emb + (size_t)tok * EMBD))[xq];
        }

        // ---- partial acc += W_hh . h over my 64-k segment ----
        #pragma unroll 4
        for (int k = 0; k < SEGK; k += 4) {
            unsigned long long Z01a, Z23a, Z01b, Z23b;
            LDS2U64(Z01a, Z23a, zkA + k * 4);
            LDS2U64(Z01b, Z23b, zkB + k * 4);
            #pragma unroll
            for (int j = 0; j < 4; j++) {
                unsigned long long W01, W23;
                LDS2U64(W01, W23, wk + (uint32_t)(j * WJ + k) * 4u);
                FMA2(A[j][0], W01, Z01a); FMA2(A[j][0], W23, Z23a);
                FMA2(A[j][1], W01, Z01b); FMA2(A[j][1], W23, Z23b);
            }
        }
        // write partial gate sums (lo+hi of k-split accumulators)
        #pragma unroll
        for (int j = 0; j < 4; j++) {
            float ga = __uint_as_float((uint32_t)A[j][0]) +
                       __uint_as_float((uint32_t)(A[j][0] >> 32));
            float gb = __uint_as_float((uint32_t)A[j][1]) +
                       __uint_as_float((uint32_t)(A[j][1] >> 32));
            gpb[(4 * rg + j) * GSTR + bq]     = ga;
            gpb[(4 * rg + j) * GSTR + bq + 2] = gb;
        }
        __syncthreads();

        // ---- phase 2 (tid < 128): reduce 4 partials + bias, activations ----
        if (tid < 128) {
            float gate[4];
            #pragma unroll
            for (int g = 0; g < 4; g++) {
                int r = g * UPC + u_l;
                float s = bs[r];
                #pragma unroll
                for (int sg = 0; sg < NSEG; sg++)
                    s += gp[sg * GSEG + r * GSTR + b2];
                gate[g] = s;
            }
            float iv = sigf(gate[0]), fv = sigf(gate[1]);
            float gv = tanha(gate[2]), ov = sigf(gate[3]);
            float cn = fmaf(fv, c_r, iv * gv);
            float hn = ov * tanha(cn);
            if (t < mylen) { c_r = cn; h_r = hn; }
            g_H[(t + 1) & 1][bg * HID + uu] = h_r;
        }
        __syncthreads();   // all g_H stores issued CTA-wide

        // ---- publish: release-store orders prior global writes ----
        if (tid == 0) {
            asm volatile("st.release.gpu.b32 [%0], %1;"
                         :: "l"(&g_flag[bsl][us]), "r"(t + 1) : "memory");
        }

        if (t + 1 < maxlen) {
            // STS the prefetched xe(t+1) (warp 0)
            if (do_xe) {
                *(float4*)(z_s + xb * ZPAD + xq * 4) = xe_pf;
            }
            // tight acquire spin on the 8 producers (warp 1 — off the xe path)
            if (tid >= 32 && tid < 32 + USLICE) {
                const int* f = &g_flag[bsl][tid - 32];
                while (ld_acq(f) < t + 1) { }
            }
            __syncthreads();

            // prefetch h(t): one float4 per thread (covered by input GEMM)
            float4 p0;
            {
                const float4* src = (const float4*)(g_H[(t + 1) & 1] + bb0 * HID);
                asm volatile("ld.volatile.global.v4.f32 {%0,%1,%2,%3}, [%4];"
                             : "=f"(p0.x), "=f"(p0.y), "=f"(p0.z), "=f"(p0.w)
                             : "l"(src + tid));
            }
            // reset partials; seg0 folds in the xe GEMM for t+1
            #pragma unroll
            for (int j = 0; j < 4; j++) { A[j][0] = 0ull; A[j][1] = 0ull; }
            if (seg == 0) {
                #pragma unroll
                for (int k = 0; k < EMBD; k += 4) {
                    unsigned long long Z01a, Z23a, Z01b, Z23b;
                    LDS2U64(Z01a, Z23a, zA + k * 4);
                    LDS2U64(Z01b, Z23b, zB + k * 4);
                    #pragma unroll
                    for (int j = 0; j < 4; j++) {
                        unsigned long long W01, W23;
                        LDS2U64(W01, W23, wbase + (uint32_t)(j * WJ + k) * 4u);
                        FMA2(A[j][0], W01, Z01a); FMA2(A[j][0], W23, Z23a);
                        FMA2(A[j][1], W01, Z01b); FMA2(A[j][1], W23, Z23b);
                    }
                }
            }
            // STS the prefetched h fragment
            {
                int b0i = tid >> 6;                 // 0..3
                int u40 = (tid & 63) * 4;           // 0..252
                *(float4*)(z_s + b0i * ZPAD + EMBD + u40) = p0;
            }
            __syncthreads();
        }
    }

    // final frozen h == reference out[:, -1, :]
    if (tid < 128) out[bg * HID + uu] = h_r;
}

extern "C" void kernel_launch(void* const* d_in, const int* in_sizes, int n_in,
                              void* d_out, int out_size) {
    const int*   x       = (const int*)d_in[0];
    const int*   lengths = (const int*)d_in[1];
    const float* emb     = (const float*)d_in[2];
    const float* W_ih    = (const float*)d_in[3];
    const float* W_hh    = (const float*)d_in[4];
    const float* b_ih    = (const float*)d_in[5];
    const float* b_hh    = (const float*)d_in[6];
    float* out = (float*)d_out;

    const int smem_bytes = SM_FLOATS * (int)sizeof(float) + 32;

    cudaFuncSetAttribute(lstm_persist_kernel,
                         cudaFuncAttributeMaxDynamicSharedMemorySize, smem_bytes);

    lstm_init_kernel<<<1, 128>>>();
    lstm_persist_kernel<<<NCTA, NTHREADS, smem_bytes>>>(
        x, lengths, emb, W_ih, W_hh, b_ih, b_hh, out);
}